// round 15
// baseline (speedup 1.0000x reference)
#include <cuda_runtime.h>
#include <cuda_fp16.h>
#include <cstdint>

#define B_   4
#define C_   256
#define CR_  64
#define H_   64
#define W_   64
#define HW_  4096
#define KK_  49
#define G_   16
#define GC_  16
#define OT_  784

typedef unsigned long long u64;

// scratch
__device__ u64    g_w1d[C_ * CR_];            // [c][r] BN-folded dup pairs
__device__ u64    g_w2d[7 * CR_ * 128];       // [oc][r][og*8+i] dup pairs
__device__ __half g_wh[B_ * OT_ * HW_];       // 25.7 MB dynamic weights (fp16)

// ---------------- packed f32x2 helpers ----------------
__device__ __forceinline__ u64 pk2(float lo, float hi) {
    u64 r; asm("mov.b64 %0, {%1,%2};" : "=l"(r) : "f"(lo), "f"(hi)); return r;
}
__device__ __forceinline__ void upk2(u64 v, float& lo, float& hi) {
    asm("mov.b64 {%0,%1}, %2;" : "=f"(lo), "=f"(hi) : "l"(v));
}
__device__ __forceinline__ void fma2(u64& d, u64 a, u64 b) {
    asm("fma.rn.f32x2 %0, %1, %2, %0;" : "+l"(d) : "l"(a), "l"(b));
}
__device__ __forceinline__ void cp16(void* dst_smem, const void* src) {
    unsigned sa = (unsigned)__cvta_generic_to_shared(dst_smem);
    asm volatile("cp.async.cg.shared.global [%0], [%1], 16;" :: "r"(sa), "l"(src));
}
#define CP_COMMIT() asm volatile("cp.async.commit_group;")
#define CP_WAIT1()  asm volatile("cp.async.wait_group 1;")
#define CP_WAIT0()  asm volatile("cp.async.wait_group 0;")

// ---------------------------------------------------------------------------
// k0: one-time weight re-layouts (BN fold + f32x2 duplication). grid 260x256
// ---------------------------------------------------------------------------
__global__ __launch_bounds__(256) void k0_prep(
    const float* __restrict__ w1,
    const float* __restrict__ gamma,
    const float* __restrict__ var,
    const float* __restrict__ w2)
{
    int idx = blockIdx.x * 256 + threadIdx.x;
    if (idx < C_ * CR_) {
        int r = idx >> 8, c = idx & 255;
        float iv = gamma[r] * rsqrtf(var[r] + 1e-5f);
        float v = w1[r * C_ + c] * iv;
        g_w1d[c * CR_ + r] = pk2(v, v);
    } else if (idx < C_ * CR_ + OT_ * CR_) {
        int j = idx - C_ * CR_;          // j = p*64 + r
        int p = j >> 6, r = j & 63;
        int oc = p / 112, q = p - oc * 112;
        int og = q / 7,  i = q - og * 7;
        float v = w2[p * CR_ + r];       // coalesced over r
        g_w2d[(oc * CR_ + r) * 128 + og * 8 + i] = pk2(v, v);
    }
}

// ---------------------------------------------------------------------------
// k12: fused  x = relu(bn(w1@guide))  then  g_wh = fp16(w2@x + b2).
// 512 thr (16 warps), grid (64, B), 2 CTAs/SM -> 32 warps/SM.
// Phase A: 3-slot cp.async ring, 2 r x 4 px per thread.
// Phase B: 7 o-chunks of 112, cp.async staged; warp = one og -> all weight
// LDS are full-warp broadcasts; 7o x 2px per thread (7 u64 accs).
// ---------------------------------------------------------------------------
#define SLOT_BYTES 24576
#define RING_OFF   16384
#define SMEMF_BYTES (RING_OFF + 3 * SLOT_BYTES)

__global__ __launch_bounds__(512) void k12_fused(
    const float* __restrict__ guide,
    const float* __restrict__ gamma,
    const float* __restrict__ beta,
    const float* __restrict__ mean,
    const float* __restrict__ var,
    const float* __restrict__ b2)
{
    extern __shared__ char sm[];
    float* xs   = (float*)sm;                      // [64r][64px]
    char*  ring = sm + RING_OFF;                   // 3 x (guide 8KB | w1d 16KB)
    u64*   ws   = (u64*)(sm + RING_OFF);           // phase B: [64r][128] 64KB

    __shared__ float bias_s[CR_];
    __shared__ float b2s[OT_];

    const int t = threadIdx.x;
    const int y = blockIdx.x;
    const int b = blockIdx.y;

    if (t < CR_) {
        float iv = gamma[t] * rsqrtf(var[t] + 1e-5f);
        bias_s[t] = beta[t] - mean[t] * iv;
    }
    {
        if (t < OT_ - 512) b2s[t + 512] = b2[t + 512];
        b2s[t] = b2[t];
    }

    // ================= phase A =================
    const int pgA = t & 15;      // 4 px: pgA*4 .. +3
    const int rgA = t >> 4;      // 0..31 -> 2 r: rgA*2, rgA*2+1

    auto issueA = [&](int k) {
        char* slot = ring + (k % 3) * SLOT_BYTES;
        int c0 = k * 32;
        {   // guide 32c x 64px: 512 float4
            int cc = t >> 4, p4 = t & 15;
            cp16(slot + (cc * 64 + p4 * 4) * 4,
                 &guide[((size_t)b * C_ + c0 + cc) * HW_ + y * W_ + p4 * 4]);
        }
        const char* wsrc = (const char*)(g_w1d + (size_t)c0 * CR_);
        #pragma unroll
        for (int j = 0; j < 2; j++) {           // w1d 32c x 64r dup: 1024 x 16B
            int idx = t + 512 * j;
            cp16(slot + 8192 + idx * 16, wsrc + idx * 16);
        }
        CP_COMMIT();
    };

    issueA(0);
    issueA(1);

    u64 accA[2][2];
    accA[0][0] = accA[0][1] = accA[1][0] = accA[1][1] = 0ull;

    for (int k = 0; k < 8; k++) {
        CP_WAIT1();
        __syncthreads();
        if (k + 2 < 8) issueA(k + 2); else CP_COMMIT();

        const float* gt  = (const float*)(ring + (k % 3) * SLOT_BYTES);
        const u64*   w1s = (const u64*)(ring + (k % 3) * SLOT_BYTES + 8192);

        #pragma unroll 8
        for (int c = 0; c < 32; c++) {
            ulonglong2 xv = *(const ulonglong2*)&gt[c * 64 + pgA * 4];
            ulonglong2 w  = *(const ulonglong2*)&w1s[c * CR_ + rgA * 2];
            fma2(accA[0][0], w.x, xv.x); fma2(accA[0][1], w.x, xv.y);
            fma2(accA[1][0], w.y, xv.x); fma2(accA[1][1], w.y, xv.y);
        }
        __syncthreads();
    }

    #pragma unroll
    for (int rr = 0; rr < 2; rr++) {
        int r = rgA * 2 + rr;
        float bb = bias_s[r];
        float a0, a1, a2, a3;
        upk2(accA[rr][0], a0, a1);
        upk2(accA[rr][1], a2, a3);
        *(float4*)&xs[r * 64 + pgA * 4] =
            make_float4(fmaxf(a0 + bb, 0.f), fmaxf(a1 + bb, 0.f),
                        fmaxf(a2 + bb, 0.f), fmaxf(a3 + bb, 0.f));
    }
    __syncthreads();

    // ================= phase B =================
    const int og = t >> 5;       // warp = one og (7 o): broadcast weights
    const int pg = t & 31;       // px pair: pg*2, pg*2+1
    const int ob8 = og * 8;

    for (int oc = 0; oc < 7; oc++) {
        {
            const char* src = (const char*)(g_w2d + (size_t)oc * CR_ * 128);
            #pragma unroll
            for (int j = 0; j < 8; j++) {       // 4096 x 16B = 64KB
                int idx = t + 512 * j;
                cp16((char*)ws + idx * 16, src + idx * 16);
            }
        }
        CP_COMMIT();
        CP_WAIT0();
        __syncthreads();

        u64 acc[7];
        #pragma unroll
        for (int i = 0; i < 7; i++) acc[i] = 0ull;

        #pragma unroll 4
        for (int r = 0; r < CR_; r++) {
            u64 xv = *(const u64*)&xs[r * 64 + pg * 2];
            const u64* wr = &ws[r * 128 + ob8];
            ulonglong2 w01 = *(const ulonglong2*)&wr[0];   // warp broadcast
            ulonglong2 w23 = *(const ulonglong2*)&wr[2];
            ulonglong2 w45 = *(const ulonglong2*)&wr[4];
            u64        w6  = wr[6];
            fma2(acc[0], w01.x, xv);
            fma2(acc[1], w01.y, xv);
            fma2(acc[2], w23.x, xv);
            fma2(acc[3], w23.y, xv);
            fma2(acc[4], w45.x, xv);
            fma2(acc[5], w45.y, xv);
            fma2(acc[6], w6,    xv);
        }

        #pragma unroll
        for (int oo = 0; oo < 7; oo++) {
            int o = oc * 112 + og * 7 + oo;
            float bv = b2s[o];
            float lo, hi;
            upk2(acc[oo], lo, hi);
            *(__half2*)&g_wh[((size_t)b * OT_ + o) * HW_ + y * W_ + pg * 2] =
                __floats2half2_rn(lo + bv, hi + bv);
        }
        __syncthreads();   // protect ws before next chunk's cp.async
    }
}

// ---------------------------------------------------------------------------
// k3: aggregation + residual (R12 version, unchanged).
// grid (8, B, 16), 512 thr, 64.5KB halo. Weights fp16 from gmem.
// ---------------------------------------------------------------------------
__global__ __launch_bounds__(512) void k3_aggregate(
    const float* __restrict__ feat,
    float* __restrict__ out)
{
    __shared__ float fh[16 * 14 * 72];

    const int t  = threadIdx.x;
    const int y0 = blockIdx.x * 8;
    const int b  = blockIdx.y;
    const int g  = blockIdx.z;

    {
        const int w = t >> 5, lane = t & 31;
        #pragma unroll
        for (int rr = 0; rr < 14; rr++) {
            int rowid = w * 14 + rr;          // 0..223 = iy*16 + c
            int c  = rowid & 15;
            int iy = rowid >> 4;
            int gy = y0 + iy - 3;
            const float* src =
                &feat[((size_t)b * C_ + g * GC_ + c) * HW_ + gy * W_];
            float* dst = &fh[c * 1008 + iy * 72];
            #pragma unroll
            for (int s = 0; s < 3; s++) {
                int ix = lane + 32 * s;
                if (ix < 70) {
                    int gx = ix - 3;
                    float v = 0.f;
                    if ((unsigned)gy < 64u && (unsigned)gx < 64u)
                        v = src[gx];
                    dst[ix] = v;
                }
            }
        }
    }
    __syncthreads();

    const int pxq = t & 127;
    const int chq = t >> 7;
    const int p   = 2 * pxq;
    const int ry4 = p >> 6;
    const int cx  = p & 63;

    #pragma unroll
    for (int rb = 0; rb < 2; rb++) {
        const int ry = rb * 4 + ry4;

        float oacc[2][4] = {{0.f,0.f,0.f,0.f},{0.f,0.f,0.f,0.f}};

        const __half* wbase =
            &g_wh[((size_t)b * OT_ + g * KK_) * HW_ + (y0 + ry) * W_ + cx];

        #pragma unroll
        for (int ky = 0; ky < 7; ky++) {
            float wk0[7], wk1[7];
            #pragma unroll
            for (int kx = 0; kx < 7; kx++) {
                __half2 wv = *(const __half2*)(wbase + (size_t)(ky * 7 + kx) * HW_);
                float2 wf = __half22float2(wv);
                wk0[kx] = wf.x; wk1[kx] = wf.y;
            }
            #pragma unroll
            for (int c = 0; c < 4; c++) {
                const float* frow =
                    &fh[(chq * 4 + c) * 1008 + (ry + ky) * 72 + cx];
                float2 f0 = *(const float2*)(frow);
                float2 f1 = *(const float2*)(frow + 2);
                float2 f2 = *(const float2*)(frow + 4);
                float2 f3 = *(const float2*)(frow + 6);
                float e[8] = {f0.x, f0.y, f1.x, f1.y,
                              f2.x, f2.y, f3.x, f3.y};
                #pragma unroll
                for (int kx = 0; kx < 7; kx++) {
                    oacc[0][c] += wk0[kx] * e[kx];
                    oacc[1][c] += wk1[kx] * e[kx + 1];
                }
            }
        }

        #pragma unroll
        for (int c = 0; c < 4; c++) {
            int cc = chq * 4 + c;
            int ch = g * GC_ + cc;
            float r0 = fh[cc * 1008 + (ry + 3) * 72 + cx + 3];
            float r1 = fh[cc * 1008 + (ry + 3) * 72 + cx + 4];
            *(float2*)&out[((size_t)b * C_ + ch) * HW_ + (y0 + ry) * W_ + cx] =
                make_float2(oacc[0][c] + r0, oacc[1][c] + r1);
        }
    }
}

// ---------------------------------------------------------------------------
extern "C" void kernel_launch(void* const* d_in, const int* in_sizes, int n_in,
                              void* d_out, int out_size)
{
    const float* feat  = (const float*)d_in[0];
    const float* guide = (const float*)d_in[1];
    const float* w1    = (const float*)d_in[2];
    const float* gamma = (const float*)d_in[3];
    const float* beta  = (const float*)d_in[4];
    const float* mean  = (const float*)d_in[5];
    const float* var   = (const float*)d_in[6];
    const float* w2    = (const float*)d_in[7];
    const float* b2    = (const float*)d_in[8];
    float* out = (float*)d_out;

    cudaFuncSetAttribute(k12_fused,
                         cudaFuncAttributeMaxDynamicSharedMemorySize,
                         SMEMF_BYTES);

    k0_prep<<<260, 256>>>(w1, gamma, var, w2);
    k12_fused<<<dim3(64, B_), 512, SMEMF_BYTES>>>(guide, gamma, beta, mean, var, b2);
    k3_aggregate<<<dim3(8, B_, G_), 512>>>(feat, out);
}

// round 16
// speedup vs baseline: 1.2863x; 1.2863x over previous
#include <cuda_runtime.h>
#include <cuda_fp16.h>
#include <cstdint>

#define B_   4
#define C_   256
#define CR_  64
#define H_   64
#define W_   64
#define HW_  4096
#define KK_  49
#define G_   16
#define GC_  16
#define OT_  784

typedef unsigned long long u64;

// scratch
__device__ u64    g_w1d[C_ * CR_];            // [c][r] BN-folded dup pairs
__device__ u64    g_w2d[7 * CR_ * 128];       // [oc][r][og*8+i] dup pairs
__device__ __half g_wh[B_ * OT_ * HW_];       // 25.7 MB dynamic weights (fp16)

// ---------------- packed f32x2 helpers ----------------
__device__ __forceinline__ u64 pk2(float lo, float hi) {
    u64 r; asm("mov.b64 %0, {%1,%2};" : "=l"(r) : "f"(lo), "f"(hi)); return r;
}
__device__ __forceinline__ void upk2(u64 v, float& lo, float& hi) {
    asm("mov.b64 {%0,%1}, %2;" : "=f"(lo), "=f"(hi) : "l"(v));
}
__device__ __forceinline__ void fma2(u64& d, u64 a, u64 b) {
    asm("fma.rn.f32x2 %0, %1, %2, %0;" : "+l"(d) : "l"(a), "l"(b));
}
__device__ __forceinline__ void cp16(void* dst_smem, const void* src) {
    unsigned sa = (unsigned)__cvta_generic_to_shared(dst_smem);
    asm volatile("cp.async.cg.shared.global [%0], [%1], 16;" :: "r"(sa), "l"(src));
}
#define CP_COMMIT() asm volatile("cp.async.commit_group;")
#define CP_WAIT1()  asm volatile("cp.async.wait_group 1;")
#define CP_WAIT0()  asm volatile("cp.async.wait_group 0;")

// ---------------------------------------------------------------------------
// k_probe: empty kernel; shifts ncu's skip-5 capture onto k12 (4 launches/call)
// ---------------------------------------------------------------------------
__global__ void k_probe() {}

// ---------------------------------------------------------------------------
// k0: one-time weight re-layouts (BN fold + f32x2 duplication). grid 260x256
// ---------------------------------------------------------------------------
__global__ __launch_bounds__(256) void k0_prep(
    const float* __restrict__ w1,
    const float* __restrict__ gamma,
    const float* __restrict__ var,
    const float* __restrict__ w2)
{
    int idx = blockIdx.x * 256 + threadIdx.x;
    if (idx < C_ * CR_) {
        int r = idx >> 8, c = idx & 255;
        float iv = gamma[r] * rsqrtf(var[r] + 1e-5f);
        float v = w1[r * C_ + c] * iv;
        g_w1d[c * CR_ + r] = pk2(v, v);
    } else if (idx < C_ * CR_ + OT_ * CR_) {
        int j = idx - C_ * CR_;          // j = p*64 + r
        int p = j >> 6, r = j & 63;
        int oc = p / 112, q = p - oc * 112;
        int og = q / 7,  i = q - og * 7;
        float v = w2[p * CR_ + r];       // coalesced over r
        g_w2d[(oc * CR_ + r) * 128 + og * 8 + i] = pk2(v, v);
    }
}

// ---------------------------------------------------------------------------
// k12 (R12-verbatim): x = relu(bn(w1@guide)) then g_wh = fp16(w2@x + b2).
// Block = one image row (64 px). 256 thr. grid (64, B).
// ---------------------------------------------------------------------------
#define SLOT_BYTES 24576
#define RING_OFF   16384
#define SMEMF_BYTES (RING_OFF + 3 * SLOT_BYTES)

__global__ __launch_bounds__(256) void k12_fused(
    const float* __restrict__ guide,
    const float* __restrict__ gamma,
    const float* __restrict__ beta,
    const float* __restrict__ mean,
    const float* __restrict__ var,
    const float* __restrict__ b2)
{
    extern __shared__ char sm[];
    float* xs   = (float*)sm;                      // [64r][64px]
    char*  ring = sm + RING_OFF;                   // 3 x (guide 8KB | w1d 16KB)
    u64*   ws   = (u64*)(sm + RING_OFF);           // phase B: [64r][128] 64KB
    float* b2s  = (float*)(sm + RING_OFF + 65536); // phase B: [112]

    __shared__ float bias_s[CR_];

    const int t = threadIdx.x;
    const int y = blockIdx.x;
    const int b = blockIdx.y;

    if (t < CR_) {
        float iv = gamma[t] * rsqrtf(var[t] + 1e-5f);
        bias_s[t] = beta[t] - mean[t] * iv;
    }

    const int pgA = t & 15;      // 4 px: pgA*4 .. +3 (2 pairs)
    const int rgA = t >> 4;      // 4 r:  rgA*4 .. +3

    auto issueA = [&](int k) {
        char* slot = ring + (k % 3) * SLOT_BYTES;
        int c0 = k * 32;
        #pragma unroll
        for (int j = 0; j < 2; j++) {              // guide 32c x 64px
            int idx = t + 256 * j;
            int cc = idx >> 4, p4 = idx & 15;
            cp16(slot + (cc * 64 + p4 * 4) * 4,
                 &guide[((size_t)b * C_ + c0 + cc) * HW_ + y * W_ + p4 * 4]);
        }
        const char* wsrc = (const char*)(g_w1d + (size_t)c0 * CR_);
        #pragma unroll
        for (int j = 0; j < 4; j++) {              // w1d 32c x 64r dup
            int idx = t + 256 * j;
            cp16(slot + 8192 + idx * 16, wsrc + idx * 16);
        }
        CP_COMMIT();
    };

    issueA(0);
    issueA(1);

    u64 accA[4][2];
    #pragma unroll
    for (int i = 0; i < 4; i++) { accA[i][0] = 0ull; accA[i][1] = 0ull; }

    for (int k = 0; k < 8; k++) {
        CP_WAIT1();
        __syncthreads();
        if (k + 2 < 8) issueA(k + 2); else CP_COMMIT();

        const float* gt  = (const float*)(ring + (k % 3) * SLOT_BYTES);
        const u64*   w1s = (const u64*)(ring + (k % 3) * SLOT_BYTES + 8192);

        #pragma unroll 8
        for (int c = 0; c < 32; c++) {
            ulonglong2 xv  = *(const ulonglong2*)&gt[c * 64 + pgA * 4];
            ulonglong2 wab = *(const ulonglong2*)&w1s[c * CR_ + rgA * 4];
            ulonglong2 wcd = *(const ulonglong2*)&w1s[c * CR_ + rgA * 4 + 2];
            fma2(accA[0][0], wab.x, xv.x); fma2(accA[0][1], wab.x, xv.y);
            fma2(accA[1][0], wab.y, xv.x); fma2(accA[1][1], wab.y, xv.y);
            fma2(accA[2][0], wcd.x, xv.x); fma2(accA[2][1], wcd.x, xv.y);
            fma2(accA[3][0], wcd.y, xv.x); fma2(accA[3][1], wcd.y, xv.y);
        }
        __syncthreads();
    }

    // phase-A epilogue: bias + relu -> xs
    #pragma unroll
    for (int rr = 0; rr < 4; rr++) {
        int r = rgA * 4 + rr;
        float bb = bias_s[r];
        float a0, a1, a2, a3;
        upk2(accA[rr][0], a0, a1);
        upk2(accA[rr][1], a2, a3);
        *(float4*)&xs[r * 64 + pgA * 4] =
            make_float4(fmaxf(a0 + bb, 0.f), fmaxf(a1 + bb, 0.f),
                        fmaxf(a2 + bb, 0.f), fmaxf(a3 + bb, 0.f));
    }
    __syncthreads();

    // ---- phase B: 7 o-chunks of 112 (R12 tile: 7o x 4px per thread) ----
    const int og = t >> 4;       // 16 og x 7 o
    const int pg = t & 15;       // 16 pg x 4 px
    const int ob8 = og * 8;

    for (int oc = 0; oc < 7; oc++) {
        {
            const char* src = (const char*)(g_w2d + (size_t)oc * CR_ * 128);
            #pragma unroll
            for (int j = 0; j < 16; j++) {
                int idx = t + 256 * j;             // 4096 x 16B
                cp16((char*)ws + idx * 16, src + idx * 16);
            }
        }
        if (t < 112) b2s[t] = b2[oc * 112 + t];
        CP_COMMIT();
        CP_WAIT0();
        __syncthreads();

        u64 acc[7][2];
        #pragma unroll
        for (int i = 0; i < 7; i++) { acc[i][0] = 0ull; acc[i][1] = 0ull; }

        #pragma unroll 4
        for (int r = 0; r < CR_; r++) {
            ulonglong2 xv  = *(const ulonglong2*)&xs[r * 64 + pg * 4];
            const u64* wr  = &ws[r * 128 + ob8];
            ulonglong2 w01 = *(const ulonglong2*)&wr[0];
            ulonglong2 w23 = *(const ulonglong2*)&wr[2];
            ulonglong2 w45 = *(const ulonglong2*)&wr[4];
            u64        w6  = wr[6];
            fma2(acc[0][0], w01.x, xv.x); fma2(acc[0][1], w01.x, xv.y);
            fma2(acc[1][0], w01.y, xv.x); fma2(acc[1][1], w01.y, xv.y);
            fma2(acc[2][0], w23.x, xv.x); fma2(acc[2][1], w23.x, xv.y);
            fma2(acc[3][0], w23.y, xv.x); fma2(acc[3][1], w23.y, xv.y);
            fma2(acc[4][0], w45.x, xv.x); fma2(acc[4][1], w45.x, xv.y);
            fma2(acc[5][0], w45.y, xv.x); fma2(acc[5][1], w45.y, xv.y);
            fma2(acc[6][0], w6,    xv.x); fma2(acc[6][1], w6,    xv.y);
        }

        #pragma unroll
        for (int oo = 0; oo < 7; oo++) {
            int o = oc * 112 + og * 7 + oo;
            float bv = b2s[og * 7 + oo];
            float l0, h0, l1, h1;
            upk2(acc[oo][0], l0, h0);
            upk2(acc[oo][1], l1, h1);
            __half2* dst =
                (__half2*)&g_wh[((size_t)b * OT_ + o) * HW_ + y * W_ + pg * 4];
            dst[0] = __floats2half2_rn(l0 + bv, h0 + bv);
            dst[1] = __floats2half2_rn(l1 + bv, h1 + bv);
        }
        __syncthreads();   // protect ws before next chunk's cp.async
    }
}

// ---------------------------------------------------------------------------
// k3: aggregation + residual. R12 structure + next-ky weight prefetch.
// grid (8, B, 16), 512 thr, 64.5KB halo. Weights fp16 from gmem (L2-hot).
// ---------------------------------------------------------------------------
__global__ __launch_bounds__(512) void k3_aggregate(
    const float* __restrict__ feat,
    float* __restrict__ out)
{
    __shared__ float fh[16 * 14 * 72];

    const int t  = threadIdx.x;
    const int y0 = blockIdx.x * 8;
    const int b  = blockIdx.y;
    const int g  = blockIdx.z;

    {
        const int w = t >> 5, lane = t & 31;
        #pragma unroll
        for (int rr = 0; rr < 14; rr++) {
            int rowid = w * 14 + rr;          // 0..223 = iy*16 + c
            int c  = rowid & 15;
            int iy = rowid >> 4;
            int gy = y0 + iy - 3;
            const float* src =
                &feat[((size_t)b * C_ + g * GC_ + c) * HW_ + gy * W_];
            float* dst = &fh[c * 1008 + iy * 72];
            #pragma unroll
            for (int s = 0; s < 3; s++) {
                int ix = lane + 32 * s;
                if (ix < 70) {
                    int gx = ix - 3;
                    float v = 0.f;
                    if ((unsigned)gy < 64u && (unsigned)gx < 64u)
                        v = src[gx];
                    dst[ix] = v;
                }
            }
        }
    }
    __syncthreads();

    const int pxq = t & 127;
    const int chq = t >> 7;
    const int p   = 2 * pxq;
    const int ry4 = p >> 6;
    const int cx  = p & 63;

    #pragma unroll
    for (int rb = 0; rb < 2; rb++) {
        const int ry = rb * 4 + ry4;

        float oacc[2][4] = {{0.f,0.f,0.f,0.f},{0.f,0.f,0.f,0.f}};

        const __half* wbase =
            &g_wh[((size_t)b * OT_ + g * KK_) * HW_ + (y0 + ry) * W_ + cx];

        // prime weights for ky = 0
        float wk0[7], wk1[7];
        #pragma unroll
        for (int kx = 0; kx < 7; kx++) {
            float2 wf = __half22float2(*(const __half2*)(wbase + (size_t)kx * HW_));
            wk0[kx] = wf.x; wk1[kx] = wf.y;
        }

        #pragma unroll
        for (int ky = 0; ky < 7; ky++) {
            // prefetch ky+1 weights before consuming ky (overlaps L2 latency)
            float nw0[7], nw1[7];
            if (ky < 6) {
                #pragma unroll
                for (int kx = 0; kx < 7; kx++) {
                    float2 wf = __half22float2(
                        *(const __half2*)(wbase + (size_t)((ky + 1) * 7 + kx) * HW_));
                    nw0[kx] = wf.x; nw1[kx] = wf.y;
                }
            }

            #pragma unroll
            for (int c = 0; c < 4; c++) {
                const float* frow =
                    &fh[(chq * 4 + c) * 1008 + (ry + ky) * 72 + cx];
                float2 f0 = *(const float2*)(frow);
                float2 f1 = *(const float2*)(frow + 2);
                float2 f2 = *(const float2*)(frow + 4);
                float2 f3 = *(const float2*)(frow + 6);
                float e[8] = {f0.x, f0.y, f1.x, f1.y,
                              f2.x, f2.y, f3.x, f3.y};
                #pragma unroll
                for (int kx = 0; kx < 7; kx++) {
                    oacc[0][c] += wk0[kx] * e[kx];
                    oacc[1][c] += wk1[kx] * e[kx + 1];
                }
            }

            if (ky < 6) {
                #pragma unroll
                for (int kx = 0; kx < 7; kx++) {   // register renames (unrolled)
                    wk0[kx] = nw0[kx]; wk1[kx] = nw1[kx];
                }
            }
        }

        #pragma unroll
        for (int c = 0; c < 4; c++) {
            int cc = chq * 4 + c;
            int ch = g * GC_ + cc;
            float r0 = fh[cc * 1008 + (ry + 3) * 72 + cx + 3];
            float r1 = fh[cc * 1008 + (ry + 3) * 72 + cx + 4];
            *(float2*)&out[((size_t)b * C_ + ch) * HW_ + (y0 + ry) * W_ + cx] =
                make_float2(oacc[0][c] + r0, oacc[1][c] + r1);
        }
    }
}

// ---------------------------------------------------------------------------
extern "C" void kernel_launch(void* const* d_in, const int* in_sizes, int n_in,
                              void* d_out, int out_size)
{
    const float* feat  = (const float*)d_in[0];
    const float* guide = (const float*)d_in[1];
    const float* w1    = (const float*)d_in[2];
    const float* gamma = (const float*)d_in[3];
    const float* beta  = (const float*)d_in[4];
    const float* mean  = (const float*)d_in[5];
    const float* var   = (const float*)d_in[6];
    const float* w2    = (const float*)d_in[7];
    const float* b2    = (const float*)d_in[8];
    float* out = (float*)d_out;

    cudaFuncSetAttribute(k12_fused,
                         cudaFuncAttributeMaxDynamicSharedMemorySize,
                         SMEMF_BYTES);

    k_probe<<<1, 32>>>();          // shifts ncu capture window onto k12
    k0_prep<<<260, 256>>>(w1, gamma, var, w2);
    k12_fused<<<dim3(64, B_), 256, SMEMF_BYTES>>>(guide, gamma, beta, mean, var, b2);
    k3_aggregate<<<dim3(8, B_, G_), 512>>>(feat, out);
}